// round 17
// baseline (speedup 1.0000x reference)
#include <cuda_runtime.h>
#include <cuda_fp16.h>
#include <cstdint>
#include <math.h>

#define T_TOKENS 8192
#define H_DIM    512
#define I_DIM    1024
#define E_NUM    8
#define CAP      T_TOKENS                // per-expert capacity
#define KC       64                      // K elems per stage (128B rows)

// ---------------- smem layout -------------------------------------------------
#define ROWB      144
#define TILE_SZ   (128 * ROWB)           // 18432 B
#define OFF_A     0
#define OFF_B     TILE_SZ
#define STG_BYTES (2 * TILE_SZ)          // 36864 B
#define NSTAGE    3
#define SMEM_BYTES (NSTAGE * STG_BYTES)  // 110592 B -> 2 CTAs/SM

// ---------------- PTX helpers ---------------------------------------------------
__device__ __forceinline__ uint32_t smem_to_u32(const void* p) {
    uint32_t a;
    asm("{ .reg .u64 t; cvta.to.shared.u64 t, %1; cvt.u32.u64 %0, t; }" : "=r"(a) : "l"(p));
    return a;
}
__device__ __forceinline__ void cp16(uint32_t s, const void* g) {
    asm volatile("cp.async.cg.shared.global [%0], [%1], 16;" :: "r"(s), "l"(g));
}
#define CP_COMMIT() asm volatile("cp.async.commit_group;" ::: "memory")
#define CP_WAIT1()  asm volatile("cp.async.wait_group 1;" ::: "memory")
#define CP_WAIT0()  asm volatile("cp.async.wait_group 0;" ::: "memory")

__device__ __forceinline__ void ldsm4(uint32_t* r, uint32_t a) {
    asm volatile("ldmatrix.sync.aligned.m8n8.x4.shared.b16 {%0,%1,%2,%3}, [%4];"
        : "=r"(r[0]), "=r"(r[1]), "=r"(r[2]), "=r"(r[3]) : "r"(a));
}
__device__ __forceinline__ void mma_f16(float* c, const uint32_t* a, const uint32_t* b) {
    asm volatile("mma.sync.aligned.m16n8k16.row.col.f32.f16.f16.f32 "
        "{%0,%1,%2,%3}, {%4,%5,%6,%7}, {%8,%9}, {%0,%1,%2,%3};"
        : "+f"(c[0]), "+f"(c[1]), "+f"(c[2]), "+f"(c[3])
        : "r"(a[0]), "r"(a[1]), "r"(a[2]), "r"(a[3]), "r"(b[0]), "r"(b[1]));
}

// ---------------- scratch (device globals) -------------------------------------
__device__ int   g_count[E_NUM];
__device__ int   g_list_tok[E_NUM * CAP];
__device__ float g_list_w[E_NUM * CAP];

__device__ __half g_xh[(size_t)T_TOKENS * H_DIM];
__device__ __half g_w1t[(size_t)E_NUM * I_DIM * H_DIM];   // [e][n=I][k=H]
__device__ __half g_w2t[(size_t)E_NUM * H_DIM * I_DIM];   // [e][n=H][k=I]
__device__ __half g_h[(size_t)E_NUM * CAP * I_DIM];

// ---------------- wconv tiles -----------------------------------------------------
__device__ __forceinline__ void wconv_tile256(const float* __restrict__ W,
                                              __half* __restrict__ wh,
                                              int K, int N, int e, int k0, int n0,
                                              float (*s)[65]) {
    int tid = threadIdx.x;
    const float* src = W + (size_t)e * K * N + (size_t)k0 * N + n0;
    int r = tid >> 2, c = tid & 3;
    const float4* row4 = reinterpret_cast<const float4*>(src + (size_t)r * N);
    #pragma unroll
    for (int i = 0; i < 4; i++) {
        int c4 = c + 4 * i;
        float4 v = row4[c4];
        s[r][c4 * 4 + 0] = v.x;
        s[r][c4 * 4 + 1] = v.y;
        s[r][c4 * 4 + 2] = v.z;
        s[r][c4 * 4 + 3] = v.w;
    }
    __syncthreads();
    size_t ob = (size_t)e * N * K + k0;
    #pragma unroll
    for (int q = 0; q < 2; q++) {
        int t = tid + q * 256;
        int kb = t & 7;
        int n  = t >> 3;
        __half hx[8];
        #pragma unroll
        for (int j = 0; j < 8; j++)
            hx[j] = __float2half_rn(s[kb * 8 + j][n]);
        *reinterpret_cast<uint4*>(wh + ob + (size_t)(n0 + n) * K + kb * 8) =
            *reinterpret_cast<uint4*>(hx);
    }
}

__device__ __forceinline__ void wconv_tile512(const float* __restrict__ W,
                                              __half* __restrict__ wh,
                                              int K, int N, int e, int k0, int n0,
                                              float (*s)[65]) {
    int tid = threadIdx.x;
    const float* src = W + (size_t)e * K * N + (size_t)k0 * N + n0;
    int r = tid >> 3, c = tid & 7;
    const float4* row4 = reinterpret_cast<const float4*>(src + (size_t)r * N);
    #pragma unroll
    for (int i = 0; i < 2; i++) {
        int c4 = c + 8 * i;
        float4 v = row4[c4];
        s[r][c4 * 4 + 0] = v.x;
        s[r][c4 * 4 + 1] = v.y;
        s[r][c4 * 4 + 2] = v.z;
        s[r][c4 * 4 + 3] = v.w;
    }
    __syncthreads();
    size_t ob = (size_t)e * N * K + k0;
    {
        int kb = tid & 7;
        int n  = tid >> 3;
        __half hx[8];
        #pragma unroll
        for (int j = 0; j < 8; j++)
            hx[j] = __float2half_rn(s[kb * 8 + j][n]);
        *reinterpret_cast<uint4*>(wh + ob + (size_t)(n0 + n) * K + kb * 8) =
            *reinterpret_cast<uint4*>(hx);
    }
    __syncthreads();
}

// ---------------- fused aux kernel: wconv1 | router | xconv ----------------------
// grid.x = 1024 (wconv1) + 1024 (router) + 256 (xconv), 256 threads each.
__global__ void aux_kernel(const float* __restrict__ x,
                           const float* __restrict__ gw,
                           const float* __restrict__ w1,
                           float* __restrict__ logits_out) {
    __shared__ float s[64][65];
    int bid = blockIdx.x;

    if (bid < 1024) {
        // wconv1: K=H_DIM(512), N=I_DIM(1024); tiles 16(n) x 8(k) per expert
        int e = bid >> 7, t = bid & 127;
        int n0 = (t & 15) * 64, k0 = (t >> 4) * 64;
        wconv_tile256(w1, g_w1t, H_DIM, I_DIM, e, k0, n0, s);
        return;
    }

    if (bid >= 2048) {
        // ---- xconv: pure streaming fp32 -> fp16, 16 float4 per thread ----
        int xb = bid - 2048;                        // 0..255
        size_t base = ((size_t)xb * 256 + threadIdx.x) * 16;  // float index granularity 16... 
        const float4* src4 = reinterpret_cast<const float4*>(x);
        uint2* dst2 = reinterpret_cast<uint2*>(g_xh);
        // each thread: 16 consecutive float4 (64 floats), stride = grid coverage
        // total threads 65536, each 64 floats => 4.19M floats exactly.
        size_t f4base = ((size_t)xb * 256 + threadIdx.x) * 16;
        #pragma unroll
        for (int i = 0; i < 16; i++) {
            float4 v = src4[f4base + i];
            __half2 h0 = __floats2half2_rn(v.x, v.y);
            __half2 h1 = __floats2half2_rn(v.z, v.w);
            uint2 o;
            o.x = *reinterpret_cast<uint32_t*>(&h0);
            o.y = *reinterpret_cast<uint32_t*>(&h1);
            dst2[f4base + i] = o;
        }
        return;
    }

    // ---- router: logits + top-2 + scatter (no conversion) ----
    int rb = bid - 1024;               // 0..1023
    int tid = threadIdx.x;
    int warp = tid >> 5, lane = tid & 31;
    int t = rb * 8 + warp;

    float xr[16];
    #pragma unroll
    for (int j = 0; j < 16; j++) xr[j] = x[(size_t)t * H_DIM + lane + 32 * j];

    float lg[E_NUM];
    #pragma unroll
    for (int e = 0; e < E_NUM; e++) {
        float sum = 0.f;
        const float* g = gw + (size_t)e * H_DIM + lane;
        #pragma unroll
        for (int j = 0; j < 16; j++) sum = fmaf(xr[j], g[32 * j], sum);
        #pragma unroll
        for (int o = 16; o; o >>= 1) sum += __shfl_xor_sync(0xffffffffu, sum, o);
        lg[e] = sum;
    }
    if (lane == 0) {
        float m = lg[0];
        #pragma unroll
        for (int e = 1; e < E_NUM; e++) m = fmaxf(m, lg[e]);
        float p[E_NUM], sum = 0.f;
        #pragma unroll
        for (int e = 0; e < E_NUM; e++) { p[e] = expf(lg[e] - m); sum += p[e]; }
        float inv = 1.f / sum;
        #pragma unroll
        for (int e = 0; e < E_NUM; e++) {
            p[e] *= inv;
            logits_out[(size_t)t * E_NUM + e] = lg[e];
        }
        int i0 = 0;
        #pragma unroll
        for (int e = 1; e < E_NUM; e++) if (p[e] > p[i0]) i0 = e;
        int i1 = (i0 == 0) ? 1 : 0;
        #pragma unroll
        for (int e = 0; e < E_NUM; e++) if (e != i1 && e != i0 && p[e] > p[i1]) i1 = e;
        float w0 = p[i0], w1v = p[i1];
        float s2 = w0 + w1v + 1e-20f;
        w0 = (w0 / s2) * 0.5f;
        w1v = (w1v / s2) * 0.5f;
        int p0 = atomicAdd(&g_count[i0], 1);
        g_list_tok[i0 * CAP + p0] = t;  g_list_w[i0 * CAP + p0] = w0;
        int p1 = atomicAdd(&g_count[i1], 1);
        g_list_tok[i1 * CAP + p1] = t;  g_list_w[i1 * CAP + p1] = w1v;
    }
}

// ---------------- GEMM core ------------------------------------------------------
struct LoadCtx {
    const char *aP, *bP;
    uint32_t sRow, gOff, smem0;
};

__device__ __forceinline__ void issue_stage(const LoadCtx& L, int s, int k0elem) {
    uint32_t sb = L.smem0 + s * STG_BYTES + L.sRow;
    size_t gk = (size_t)k0elem * 2 + L.gOff;
    cp16(sb + OFF_A,      L.aP + gk);
    cp16(sb + OFF_A + 16, L.aP + gk + 16);
    cp16(sb + OFF_B,      L.bP + gk);
    cp16(sb + OFF_B + 16, L.bP + gk + 16);
}

__device__ __forceinline__ void compute_stage(uint32_t sb,
        const uint32_t* aOff, const uint32_t* bOff, float acc[2][4][4]) {
    #pragma unroll
    for (int ks = 0; ks < 4; ks++) {
        uint32_t a[2][4], b[2][4];
        #pragma unroll
        for (int mi = 0; mi < 2; mi++)
            ldsm4(a[mi], sb + OFF_A + aOff[mi] + ks * 32);
        #pragma unroll
        for (int nt = 0; nt < 2; nt++)
            ldsm4(b[nt], sb + OFF_B + bOff[nt] + ks * 32);
        #pragma unroll
        for (int mi = 0; mi < 2; mi++) {
            #pragma unroll
            for (int ni = 0; ni < 4; ni++) {
                int nt = ni >> 1, j = ni & 1;
                uint32_t bf[2] = { b[nt][j], b[nt][j + 2] };
                mma_f16(acc[mi][ni], a[mi], bf);
            }
        }
    }
}

// ---------------- GEMM1 (+ embedded wconv2 slice at z==E_NUM) --------------------
__global__ __launch_bounds__(512, 2) void gemm1_kernel(const float* __restrict__ b1,
                                                       const float* __restrict__ w2) {
    extern __shared__ char smem[];

    if (blockIdx.z == E_NUM) {
        float (*s)[65] = reinterpret_cast<float(*)[65]>(smem);
        int base = (blockIdx.y * 8 + blockIdx.x) * 2;   // 0..1022
        #pragma unroll
        for (int q = 0; q < 2; q++) {
            int tile = base + q;
            int e = tile >> 7, t = tile & 127;
            int n0 = (t & 7) * 64, k0 = (t >> 3) * 64;
            wconv_tile512(w2, g_w2t, I_DIM, H_DIM, e, k0, n0, s);
        }
        return;
    }

    const int e = blockIdx.z;
    const int cnt = g_count[e];
    const int m_base = blockIdx.y * 128;
    if (m_base >= cnt) return;
    const int off = e * CAP;
    const int n_base = blockIdx.x * 128;
    const int tid = threadIdx.x;
    const int w = tid >> 5, lane = tid & 31;
    const int wm = w & 3, wn = w >> 2;

    LoadCtx L;
    {
        int rowIdx = tid >> 2;
        int gm = m_base + rowIdx;
        int tok = g_list_tok[off + ((gm < cnt) ? gm : 0)];
        L.aP = (const char*)(g_xh + (size_t)tok * H_DIM);
        size_t rB = ((size_t)e * I_DIM + (n_base + rowIdx)) * H_DIM;
        L.bP = (const char*)(g_w1t + rB);
        L.gOff = (tid & 3) * 32;
        L.sRow = (uint32_t)rowIdx * ROWB + L.gOff;
        L.smem0 = smem_to_u32(smem);
    }

    uint32_t aOff[2], bOff[2];
    {
        int mat = lane >> 3, lr = lane & 7;
        uint32_t kb = (uint32_t)(lane >> 4) * 16;
        #pragma unroll
        for (int mi = 0; mi < 2; mi++)
            aOff[mi] = (uint32_t)(wm * 32 + mi * 16 + ((mat & 1) << 3) + lr) * ROWB + kb;
        #pragma unroll
        for (int nt = 0; nt < 2; nt++)
            bOff[nt] = (uint32_t)(wn * 32 + nt * 16 + ((mat & 1) << 3) + lr) * ROWB + kb;
    }

    float acc[2][4][4] = {};

    const int NC = H_DIM / KC;   // 8
    issue_stage(L, 0, 0);   CP_COMMIT();
    issue_stage(L, 1, KC);  CP_COMMIT();
    for (int c = 0; c < NC; c++) {
        if (c + 2 < NC) CP_WAIT1(); else CP_WAIT0();
        __syncthreads();
        if (c + 2 < NC) { issue_stage(L, (c + 2) % NSTAGE, (c + 2) * KC); CP_COMMIT(); }
        compute_stage(L.smem0 + (c % NSTAGE) * STG_BYTES, aOff, bOff, acc);
    }

    int qrow = lane >> 2, qcol = (lane & 3) * 2;
    #pragma unroll
    for (int mi = 0; mi < 2; mi++) {
        #pragma unroll
        for (int half = 0; half < 2; half++) {
            int row = wm * 32 + mi * 16 + qrow + half * 8;
            int gm = m_base + row;
            if (gm >= cnt) continue;
            size_t pair = (size_t)(off + gm);
            #pragma unroll
            for (int ni = 0; ni < 4; ni++) {
                int n = n_base + wn * 32 + ni * 8 + qcol;
                float v0 = fmaxf(acc[mi][ni][half * 2 + 0] + b1[e * I_DIM + n],     0.f);
                float v1 = fmaxf(acc[mi][ni][half * 2 + 1] + b1[e * I_DIM + n + 1], 0.f);
                __half2 hp = __floats2half2_rn(v0, v1);
                *reinterpret_cast<__half2*>(g_h + pair * I_DIM + n) = hp;
            }
        }
    }
}

// ---------------- GEMM2: out[tok] += wgt * (h @ W2t + b2) ------------------------
__global__ __launch_bounds__(512, 2) void gemm2_kernel(const float* __restrict__ b2,
                                                       float* __restrict__ out) {
    extern __shared__ char smem[];
    const int e = blockIdx.z;
    const int cnt = g_count[e];
    const int m_base = blockIdx.y * 128;
    if (m_base >= cnt) return;
    const int off = e * CAP;
    const int n_base = blockIdx.x * 128;
    const int tid = threadIdx.x;
    const int w = tid >> 5, lane = tid & 31;
    const int wm = w & 3, wn = w >> 2;

    LoadCtx L;
    {
        int rowIdx = tid >> 2;
        int gm = m_base + rowIdx;
        size_t pr = (size_t)(off + ((gm < cnt) ? gm : 0));
        L.aP = (const char*)(g_h + pr * I_DIM);
        size_t rB = ((size_t)e * H_DIM + (n_base + rowIdx)) * I_DIM;
        L.bP = (const char*)(g_w2t + rB);
        L.gOff = (tid & 3) * 32;
        L.sRow = (uint32_t)rowIdx * ROWB + L.gOff;
        L.smem0 = smem_to_u32(smem);
    }

    uint32_t aOff[2], bOff[2];
    {
        int mat = lane >> 3, lr = lane & 7;
        uint32_t kb = (uint32_t)(lane >> 4) * 16;
        #pragma unroll
        for (int mi = 0; mi < 2; mi++)
            aOff[mi] = (uint32_t)(wm * 32 + mi * 16 + ((mat & 1) << 3) + lr) * ROWB + kb;
        #pragma unroll
        for (int nt = 0; nt < 2; nt++)
            bOff[nt] = (uint32_t)(wn * 32 + nt * 16 + ((mat & 1) << 3) + lr) * ROWB + kb;
    }

    float acc[2][4][4] = {};

    const int NC = I_DIM / KC;   // 16
    issue_stage(L, 0, 0);   CP_COMMIT();
    issue_stage(L, 1, KC);  CP_COMMIT();
    for (int c = 0; c < NC; c++) {
        if (c + 2 < NC) CP_WAIT1(); else CP_WAIT0();
        __syncthreads();
        if (c + 2 < NC) { issue_stage(L, (c + 2) % NSTAGE, (c + 2) * KC); CP_COMMIT(); }
        compute_stage(L.smem0 + (c % NSTAGE) * STG_BYTES, aOff, bOff, acc);
    }

    int qrow = lane >> 2, qcol = (lane & 3) * 2;
    #pragma unroll
    for (int mi = 0; mi < 2; mi++) {
        #pragma unroll
        for (int half = 0; half < 2; half++) {
            int row = wm * 32 + mi * 16 + qrow + half * 8;
            int gm = m_base + row;
            if (gm >= cnt) continue;
            int tok = g_list_tok[off + gm];
            float wgt = g_list_w[off + gm];
            float* dst = out + (size_t)tok * H_DIM;
            #pragma unroll
            for (int ni = 0; ni < 4; ni++) {
                int n = n_base + wn * 32 + ni * 8 + qcol;
                atomicAdd(&dst[n],     wgt * (acc[mi][ni][half * 2 + 0] + b2[e * H_DIM + n]));
                atomicAdd(&dst[n + 1], wgt * (acc[mi][ni][half * 2 + 1] + b2[e * H_DIM + n + 1]));
            }
        }
    }
}

// ---------------- launch ----------------------------------------------------------
extern "C" void kernel_launch(void* const* d_in, const int* in_sizes, int n_in,
                              void* d_out, int out_size) {
    const float* x  = (const float*)d_in[0];
    const float* gw = (const float*)d_in[1];
    const float* w1 = (const float*)d_in[2];
    const float* b1 = (const float*)d_in[3];
    const float* w2 = (const float*)d_in[4];
    const float* b2 = (const float*)d_in[5];
    float* out = (float*)d_out;
    float* logits = out + (size_t)T_TOKENS * H_DIM;

    cudaFuncSetAttribute(gemm1_kernel, cudaFuncAttributeMaxDynamicSharedMemorySize, SMEM_BYTES);
    cudaFuncSetAttribute(gemm2_kernel, cudaFuncAttributeMaxDynamicSharedMemorySize, SMEM_BYTES);

    cudaMemsetAsync(out, 0, (size_t)T_TOKENS * H_DIM * sizeof(float), 0);
    void* cnt_ptr = nullptr;
    cudaGetSymbolAddress(&cnt_ptr, g_count);
    cudaMemsetAsync(cnt_ptr, 0, E_NUM * sizeof(int), 0);

    // fused aux: 1024 wconv1 + 1024 router + 256 xconv blocks
    aux_kernel<<<2304, 256>>>(x, gw, w1, logits);

    // gemm1 + embedded wconv2 slice (z == E_NUM)
    dim3 g1(I_DIM / 128, T_TOKENS / 128, E_NUM + 1);
    gemm1_kernel<<<g1, 512, SMEM_BYTES>>>(b1, w2);

    dim3 g2(H_DIM / 128, T_TOKENS / 128, E_NUM);
    gemm2_kernel<<<g2, 512, SMEM_BYTES>>>(b2, out);
}